// round 2
// baseline (speedup 1.0000x reference)
#include <cuda_runtime.h>
#include <math.h>

#define S_LEN 2048
#define HID 2048
#define NH 16
#define NKVH 2
#define HD 128
#define NREP 8
#define SCALING 0.08838834764831845f

// Scratch (device globals; no allocation allowed)
__device__ float g_q[S_LEN * NH * HD];      // [S][NH*HD]
__device__ float g_k[S_LEN * NKVH * HD];    // [S][NKVH*HD]
__device__ float g_v[S_LEN * NKVH * HD];    // [S][NKVH*HD]
__device__ float g_attn[S_LEN * NH * HD];   // [S][NH*HD]

// ---------------------------------------------------------------------------
// GEMM: C[M,N] = A[M,K] @ B[K,N] (+ bias). BM=BN=128, BK=16, 256 threads,
// 8x8 outputs per thread. Requires M%128==0, N%128==0, K%16==0.
// ---------------------------------------------------------------------------
__global__ __launch_bounds__(256, 2)
void gemm_kernel(const float* __restrict__ A, const float* __restrict__ B,
                 const float* __restrict__ bias, float* __restrict__ C,
                 int M, int N, int K) {
    __shared__ float As[16][128];   // transposed A tile: As[k][m]
    __shared__ float Bs[16][128];   // Bs[k][n]

    const int tid = threadIdx.x;
    const int tx = tid & 15;
    const int ty = tid >> 4;
    const int m0 = blockIdx.y * 128;
    const int n0 = blockIdx.x * 128;

    float acc[8][8];
#pragma unroll
    for (int i = 0; i < 8; i++)
#pragma unroll
        for (int j = 0; j < 8; j++) acc[i][j] = 0.0f;

    for (int k0 = 0; k0 < K; k0 += 16) {
        // Load A tile: 128 rows x 16 k = 512 float4, 2 per thread, transpose into As
#pragma unroll
        for (int e = 0; e < 2; e++) {
            int lin = tid + e * 256;        // float4 index
            int row = lin >> 2;             // 0..127
            int kq  = (lin & 3) * 4;
            float4 a = *(const float4*)&A[(size_t)(m0 + row) * K + k0 + kq];
            As[kq + 0][row] = a.x;
            As[kq + 1][row] = a.y;
            As[kq + 2][row] = a.z;
            As[kq + 3][row] = a.w;
        }
        // Load B tile: 16 rows x 128 n = 512 float4
#pragma unroll
        for (int e = 0; e < 2; e++) {
            int lin = tid + e * 256;
            int row = lin >> 5;             // 0..15
            int col = (lin & 31) * 4;
            *(float4*)&Bs[row][col] = *(const float4*)&B[(size_t)(k0 + row) * N + n0 + col];
        }
        __syncthreads();

#pragma unroll
        for (int kk = 0; kk < 16; kk++) {
            float a[8], b[8];
            *(float4*)&a[0] = *(float4*)&As[kk][ty * 8];
            *(float4*)&a[4] = *(float4*)&As[kk][ty * 8 + 4];
            *(float4*)&b[0] = *(float4*)&Bs[kk][tx * 8];
            *(float4*)&b[4] = *(float4*)&Bs[kk][tx * 8 + 4];
#pragma unroll
            for (int i = 0; i < 8; i++)
#pragma unroll
                for (int j = 0; j < 8; j++)
                    acc[i][j] += a[i] * b[j];
        }
        __syncthreads();
    }

#pragma unroll
    for (int i = 0; i < 8; i++) {
        int row = m0 + ty * 8 + i;
#pragma unroll
        for (int j = 0; j < 8; j += 4) {
            int col = n0 + tx * 8 + j;
            float4 o;
            o.x = acc[i][j];     o.y = acc[i][j + 1];
            o.z = acc[i][j + 2]; o.w = acc[i][j + 3];
            if (bias != nullptr) {
                o.x += bias[col];     o.y += bias[col + 1];
                o.z += bias[col + 2]; o.w += bias[col + 3];
            }
            *(float4*)&C[(size_t)row * N + col] = o;
        }
    }
}

// ---------------------------------------------------------------------------
// RoPE (in place). x layout [S][nh*HD]. cos/sin layout [S][HD].
// Thread handles the (d, d+64) pair for one (s, h).
// ---------------------------------------------------------------------------
__global__ void rope_kernel(float* __restrict__ x,
                            const float* __restrict__ cosp,
                            const float* __restrict__ sinp, int nh) {
    int idx = blockIdx.x * blockDim.x + threadIdx.x;
    int total = S_LEN * nh * 64;
    if (idx >= total) return;
    int d = idx & 63;
    int h = (idx >> 6) % nh;
    int s = idx / (nh * 64);
    float c1 = cosp[s * HD + d];
    float s1 = sinp[s * HD + d];
    float c2 = cosp[s * HD + d + 64];
    float s2 = sinp[s * HD + d + 64];
    float* row = x + (size_t)s * nh * HD + h * HD;
    float x1 = row[d];
    float x2 = row[d + 64];
    row[d]      = x1 * c1 - x2 * s1;   // rotate_half: first half gets -x[h:]
    row[d + 64] = x2 * c2 + x1 * s2;   // second half gets +x[:h]
}

// ---------------------------------------------------------------------------
// Causal flash attention, fp32. BM=BN=64, D=128. 256 threads.
// grid = (S/64, NH). Q-tiles processed in reverse block order for balance.
// Dynamic smem layout (floats):
//   Qs[128][68] (d-major, padded), Ks[128][68], Vs[64][128],
//   Ps[64][68], red[64][17], row_m[64], row_l[64], row_scale[64]
// ---------------------------------------------------------------------------
#define QS_OFF   0
#define KS_OFF   (128 * 68)
#define VS_OFF   (KS_OFF + 128 * 68)
#define PS_OFF   (VS_OFF + 64 * 128)
#define RED_OFF  (PS_OFF + 64 * 68)
#define RM_OFF   (RED_OFF + 64 * 17)
#define RL_OFF   (RM_OFF + 64)
#define RS_OFF   (RL_OFF + 64)
#define FLASH_SMEM_FLOATS (RS_OFF + 64)
#define FLASH_SMEM_BYTES  (FLASH_SMEM_FLOATS * 4)

__global__ __launch_bounds__(256, 1)
void flash_kernel(const float* __restrict__ Q, const float* __restrict__ Kg,
                  const float* __restrict__ Vg, float* __restrict__ O) {
    extern __shared__ float sm[];
    float* Qs = sm + QS_OFF;
    float* Ks = sm + KS_OFF;
    float* Vs = sm + VS_OFF;
    float* Ps = sm + PS_OFF;
    float* red = sm + RED_OFF;
    float* row_m = sm + RM_OFF;
    float* row_l = sm + RL_OFF;
    float* row_scale = sm + RS_OFF;

    const int tid = threadIdx.x;
    const int tx = tid & 15;
    const int ty = tid >> 4;
    const int qt = (gridDim.x - 1) - blockIdx.x;   // reversed: big blocks first
    const int h = blockIdx.y;
    const int kvh = h / NREP;
    const int s0 = qt * 64;

    // Load Q tile, transposed: Qs[d][row]
#pragma unroll
    for (int e = 0; e < 8; e++) {
        int lin = tid + e * 256;        // float4 index, 0..2047
        int row = lin >> 5;             // 0..63
        int dq = (lin & 31) * 4;        // 0..124
        float4 qv = *(const float4*)&Q[(size_t)(s0 + row) * (NH * HD) + h * HD + dq];
        Qs[(dq + 0) * 68 + row] = qv.x;
        Qs[(dq + 1) * 68 + row] = qv.y;
        Qs[(dq + 2) * 68 + row] = qv.z;
        Qs[(dq + 3) * 68 + row] = qv.w;
    }
    if (tid < 64) {
        row_m[tid] = -1e30f;
        row_l[tid] = 0.0f;
    }

    float acc[4][8];
#pragma unroll
    for (int i = 0; i < 4; i++)
#pragma unroll
        for (int c = 0; c < 8; c++) acc[i][c] = 0.0f;

    for (int jt = 0; jt <= qt; jt++) {
        const int j0 = jt * 64;
        __syncthreads();   // previous P@V done; Q load / m,l init done (first iter)

        // Load K tile transposed + V tile natural
#pragma unroll
        for (int e = 0; e < 8; e++) {
            int lin = tid + e * 256;
            int row = lin >> 5;
            int dq = (lin & 31) * 4;
            float4 kv = *(const float4*)&Kg[(size_t)(j0 + row) * (NKVH * HD) + kvh * HD + dq];
            Ks[(dq + 0) * 68 + row] = kv.x;
            Ks[(dq + 1) * 68 + row] = kv.y;
            Ks[(dq + 2) * 68 + row] = kv.z;
            Ks[(dq + 3) * 68 + row] = kv.w;
            float4 vv = *(const float4*)&Vg[(size_t)(j0 + row) * (NKVH * HD) + kvh * HD + dq];
            *(float4*)&Vs[row * 128 + dq] = vv;
        }
        __syncthreads();

        // Scores: sc[i][j] = sum_d Qs[d][ty*4+i] * Ks[d][tx*4+j]
        float sc[4][4];
#pragma unroll
        for (int i = 0; i < 4; i++)
#pragma unroll
            for (int j = 0; j < 4; j++) sc[i][j] = 0.0f;

#pragma unroll 4
        for (int kk = 0; kk < 128; kk++) {
            float4 q4 = *(const float4*)&Qs[kk * 68 + ty * 4];
            float4 k4 = *(const float4*)&Ks[kk * 68 + tx * 4];
            float qa[4] = {q4.x, q4.y, q4.z, q4.w};
            float ka[4] = {k4.x, k4.y, k4.z, k4.w};
#pragma unroll
            for (int i = 0; i < 4; i++)
#pragma unroll
                for (int j = 0; j < 4; j++)
                    sc[i][j] += qa[i] * ka[j];
        }

        // Scale + causal mask, compute per-thread row maxima
#pragma unroll
        for (int i = 0; i < 4; i++) {
            int qrow = s0 + ty * 4 + i;
            float mx = -1e30f;
#pragma unroll
            for (int j = 0; j < 4; j++) {
                int kcol = j0 + tx * 4 + j;
                float v = sc[i][j] * SCALING;
                if (kcol > qrow) v = -1e9f;
                sc[i][j] = v;
                mx = fmaxf(mx, v);
            }
            red[(ty * 4 + i) * 17 + tx] = mx;
        }
        __syncthreads();

        // Row max + rescale factor (64 threads)
        if (tid < 64) {
            float mt = red[tid * 17];
#pragma unroll
            for (int t = 1; t < 16; t++) mt = fmaxf(mt, red[tid * 17 + t]);
            float m_old = row_m[tid];
            float m_new = fmaxf(m_old, mt);
            row_scale[tid] = __expf(m_old - m_new);
            row_m[tid] = m_new;
        }
        __syncthreads();

        // exp, write P, partial sums
#pragma unroll
        for (int i = 0; i < 4; i++) {
            float m_r = row_m[ty * 4 + i];
            float s_part = 0.0f;
#pragma unroll
            for (int j = 0; j < 4; j++) {
                float p = __expf(sc[i][j] - m_r);
                Ps[(ty * 4 + i) * 68 + tx * 4 + j] = p;
                s_part += p;
            }
            red[(ty * 4 + i) * 17 + tx] = s_part;
        }
        __syncthreads();

        // l update (64 threads)
        if (tid < 64) {
            float sum = 0.0f;
#pragma unroll
            for (int t = 0; t < 16; t++) sum += red[tid * 17 + t];
            row_l[tid] = row_l[tid] * row_scale[tid] + sum;
        }

        // P @ V with accumulator rescale (no sync needed: Ps / row_scale ready)
        float rs[4];
#pragma unroll
        for (int i = 0; i < 4; i++) rs[i] = row_scale[ty * 4 + i];
#pragma unroll
        for (int i = 0; i < 4; i++)
#pragma unroll
            for (int c = 0; c < 8; c++) acc[i][c] *= rs[i];

#pragma unroll 2
        for (int j = 0; j < 64; j++) {
            float4 v0 = *(const float4*)&Vs[j * 128 + tx * 8];
            float4 v1 = *(const float4*)&Vs[j * 128 + tx * 8 + 4];
            float va[8] = {v0.x, v0.y, v0.z, v0.w, v1.x, v1.y, v1.z, v1.w};
            float p[4];
#pragma unroll
            for (int i = 0; i < 4; i++) p[i] = Ps[(ty * 4 + i) * 68 + j];
#pragma unroll
            for (int i = 0; i < 4; i++)
#pragma unroll
                for (int c = 0; c < 8; c++)
                    acc[i][c] += p[i] * va[c];
        }
    }

    __syncthreads();  // row_l final
#pragma unroll
    for (int i = 0; i < 4; i++) {
        int row = s0 + ty * 4 + i;
        float inv_l = 1.0f / row_l[ty * 4 + i];
        float4 o0, o1;
        o0.x = acc[i][0] * inv_l; o0.y = acc[i][1] * inv_l;
        o0.z = acc[i][2] * inv_l; o0.w = acc[i][3] * inv_l;
        o1.x = acc[i][4] * inv_l; o1.y = acc[i][5] * inv_l;
        o1.z = acc[i][6] * inv_l; o1.w = acc[i][7] * inv_l;
        float* dst = &O[(size_t)row * (NH * HD) + h * HD + tx * 8];
        *(float4*)&dst[0] = o0;
        *(float4*)&dst[4] = o1;
    }
}

// ---------------------------------------------------------------------------
// Launch
// ---------------------------------------------------------------------------
extern "C" void kernel_launch(void* const* d_in, const int* in_sizes, int n_in,
                              void* d_out, int out_size) {
    const float* hs   = (const float*)d_in[0];
    const float* cosp = (const float*)d_in[1];
    const float* sinp = (const float*)d_in[2];
    // d_in[3] = attention_mask (pure causal; applied analytically)
    const float* Wq = (const float*)d_in[4];
    const float* bq = (const float*)d_in[5];
    const float* Wk = (const float*)d_in[6];
    const float* bk = (const float*)d_in[7];
    const float* Wv = (const float*)d_in[8];
    const float* bv = (const float*)d_in[9];
    const float* Wo = (const float*)d_in[10];
    float* out = (float*)d_out;

    float *q, *k, *v, *attn;
    cudaGetSymbolAddress((void**)&q, g_q);
    cudaGetSymbolAddress((void**)&k, g_k);
    cudaGetSymbolAddress((void**)&v, g_v);
    cudaGetSymbolAddress((void**)&attn, g_attn);

    // Projections
    gemm_kernel<<<dim3((NH * HD) / 128, S_LEN / 128), 256>>>(hs, Wq, bq, q, S_LEN, NH * HD, HID);
    gemm_kernel<<<dim3((NKVH * HD) / 128, S_LEN / 128), 256>>>(hs, Wk, bk, k, S_LEN, NKVH * HD, HID);
    gemm_kernel<<<dim3((NKVH * HD) / 128, S_LEN / 128), 256>>>(hs, Wv, bv, v, S_LEN, NKVH * HD, HID);

    // RoPE
    rope_kernel<<<(S_LEN * NH * 64) / 256, 256>>>(q, cosp, sinp, NH);
    rope_kernel<<<(S_LEN * NKVH * 64) / 256, 256>>>(k, cosp, sinp, NKVH);

    // Attention
    cudaFuncSetAttribute(flash_kernel, cudaFuncAttributeMaxDynamicSharedMemorySize,
                         FLASH_SMEM_BYTES);
    flash_kernel<<<dim3(S_LEN / 64, NH), 256, FLASH_SMEM_BYTES>>>(q, k, v, attn);

    // Output projection
    gemm_kernel<<<dim3(HID / 128, S_LEN / 128), 256>>>(attn, Wo, nullptr, out, S_LEN, HID, NH * HD);
}

// round 6
// speedup vs baseline: 1.8157x; 1.8157x over previous
#include <cuda_runtime.h>
#include <cstdint>
#include <math.h>

#define S_LEN 2048
#define HID 2048
#define NH 16
#define NKVH 2
#define HD 128
#define NREP 8
#define SCALING 0.08838834764831845f
#define KV_STRIDE 512   // fused K|V row: [K(2*128) | V(2*128)]

// ---------------------------------------------------------------------------
// Scratch (device globals; no allocation allowed)
// ---------------------------------------------------------------------------
__device__ float g_q[S_LEN * NH * HD];          // [S][2048]
__device__ float g_kv[S_LEN * KV_STRIDE];       // [S][512]
__device__ float g_attn[S_LEN * NH * HD];       // [S][2048]
__device__ float g_wqt[HID * (NH * HD)];        // Wq^T  [2048][2048] (tf32-rounded)
__device__ float g_wkvt[KV_STRIDE * HID];       // [Wk^T ; Wv^T] [512][2048]
__device__ float g_wot[HID * (NH * HD)];        // Wo^T  [2048][2048]
__device__ float g_bkv[KV_STRIDE];              // [bk ; bv]

// ---------------------------------------------------------------------------
__device__ __forceinline__ uint32_t f2tf32(float x) {
    uint32_t r;
    asm("cvt.rna.tf32.f32 %0, %1;" : "=r"(r) : "f"(x));
    return r;
}

// ---------------------------------------------------------------------------
// Weight transpose + round-to-tf32: dst[c][r] = tf32(src[r][c]). src [R][C].
// ---------------------------------------------------------------------------
__global__ void transpose_round_kernel(const float* __restrict__ src,
                                       float* __restrict__ dst, int R, int C) {
    __shared__ float t[32][33];
    int c0 = blockIdx.x * 32, r0 = blockIdx.y * 32;
    int x = threadIdx.x, y = threadIdx.y;  // 32 x 8
#pragma unroll
    for (int e = 0; e < 4; e++) {
        int r = r0 + y + e * 8;
        t[y + e * 8][x] = src[(size_t)r * C + c0 + x];
    }
    __syncthreads();
#pragma unroll
    for (int e = 0; e < 4; e++) {
        int c = c0 + y + e * 8;
        dst[(size_t)c * R + r0 + x] = __uint_as_float(f2tf32(t[x][y + e * 8]));
    }
}

// ---------------------------------------------------------------------------
// tf32 mma.sync GEMM: C[M,N] = A[M,K] @ Bt[N,K]^T (+ bias).
// CTA tile 128x128, BK=32, 256 threads = 8 warps (4 m x 2 n), warp tile 32x64.
// Double-buffered dynamic smem; padded pitch 36 floats (bank-conflict-free).
// A tf32-rounded on load; Bt pre-rounded.
// ---------------------------------------------------------------------------
#define GP 36                       // smem pitch (floats)
#define ASZ (128 * GP)              // one A (or B) tile in floats
#define GSTAGE (2 * ASZ)            // A + B per stage
#define GEMM_SMEM_BYTES (2 * GSTAGE * 4)

__global__ __launch_bounds__(256, 1)
void gemm_mma_kernel(const float* __restrict__ A, const float* __restrict__ Bt,
                     const float* __restrict__ bias, float* __restrict__ C,
                     int M, int N, int K) {
    extern __shared__ float sm[];
    const int tid = threadIdx.x;
    const int wid = tid >> 5;
    const int lane = tid & 31;
    const int wm = wid & 3;          // 0..3  (m)
    const int wn = wid >> 2;         // 0..1  (n)
    const int m0 = blockIdx.y * 128;
    const int n0 = blockIdx.x * 128;

    float acc[2][8][4];
#pragma unroll
    for (int mt = 0; mt < 2; mt++)
#pragma unroll
        for (int nt = 0; nt < 8; nt++)
#pragma unroll
            for (int c = 0; c < 4; c++) acc[mt][nt][c] = 0.0f;

    const int nst = K >> 5;          // BK=32 stages
    float4 av[4], bv[4];

    // ---- prologue: load stage 0 ----
#pragma unroll
    for (int e = 0; e < 4; e++) {
        int lin = tid + e * 256;             // 0..1023 float4 slots
        int row = lin >> 3, q = lin & 7;
        av[e] = *(const float4*)&A[(size_t)(m0 + row) * K + q * 4];
        bv[e] = *(const float4*)&Bt[(size_t)(n0 + row) * K + q * 4];
    }
#pragma unroll
    for (int e = 0; e < 4; e++) {
        int lin = tid + e * 256;
        int row = lin >> 3, q = lin & 7;
        uint4 t;
        t.x = f2tf32(av[e].x); t.y = f2tf32(av[e].y);
        t.z = f2tf32(av[e].z); t.w = f2tf32(av[e].w);
        *(uint4*)&sm[row * GP + q * 4] = t;
        *(float4*)&sm[ASZ + row * GP + q * 4] = bv[e];
    }
    __syncthreads();

    for (int s = 0; s < nst; s++) {
        const int cur = (s & 1) * GSTAGE;
        const int nxt = ((s + 1) & 1) * GSTAGE;

        if (s + 1 < nst) {
            const int k0 = (s + 1) << 5;
#pragma unroll
            for (int e = 0; e < 4; e++) {
                int lin = tid + e * 256;
                int row = lin >> 3, q = lin & 7;
                av[e] = *(const float4*)&A[(size_t)(m0 + row) * K + k0 + q * 4];
                bv[e] = *(const float4*)&Bt[(size_t)(n0 + row) * K + k0 + q * 4];
            }
        }

        // ---- compute on cur ----
        const uint32_t* uA = (const uint32_t*)(sm + cur);
        const uint32_t* uB = (const uint32_t*)(sm + cur + ASZ);
#pragma unroll
        for (int ks = 0; ks < 4; ks++) {
            const int kk = ks * 8 + (lane & 3);
            uint32_t a[2][4], b[8][2];
#pragma unroll
            for (int mt = 0; mt < 2; mt++) {
                int r = wm * 32 + mt * 16 + (lane >> 2);
                a[mt][0] = uA[r * GP + kk];
                a[mt][1] = uA[(r + 8) * GP + kk];
                a[mt][2] = uA[r * GP + kk + 4];
                a[mt][3] = uA[(r + 8) * GP + kk + 4];
            }
#pragma unroll
            for (int nt = 0; nt < 8; nt++) {
                int ccol = wn * 64 + nt * 8 + (lane >> 2);
                b[nt][0] = uB[ccol * GP + kk];
                b[nt][1] = uB[ccol * GP + kk + 4];
            }
#pragma unroll
            for (int mt = 0; mt < 2; mt++)
#pragma unroll
                for (int nt = 0; nt < 8; nt++) {
                    asm volatile(
                        "mma.sync.aligned.m16n8k8.row.col.f32.tf32.tf32.f32 "
                        "{%0,%1,%2,%3}, {%4,%5,%6,%7}, {%8,%9}, {%0,%1,%2,%3};"
                        : "+f"(acc[mt][nt][0]), "+f"(acc[mt][nt][1]),
                          "+f"(acc[mt][nt][2]), "+f"(acc[mt][nt][3])
                        : "r"(a[mt][0]), "r"(a[mt][1]), "r"(a[mt][2]), "r"(a[mt][3]),
                          "r"(b[nt][0]), "r"(b[nt][1]));
                }
        }

        if (s + 1 < nst) {
            __syncthreads();
#pragma unroll
            for (int e = 0; e < 4; e++) {
                int lin = tid + e * 256;
                int row = lin >> 3, q = lin & 7;
                uint4 t;
                t.x = f2tf32(av[e].x); t.y = f2tf32(av[e].y);
                t.z = f2tf32(av[e].z); t.w = f2tf32(av[e].w);
                *(uint4*)&sm[nxt + row * GP + q * 4] = t;
                *(float4*)&sm[nxt + ASZ + row * GP + q * 4] = bv[e];
            }
            __syncthreads();
        }
    }

    // ---- epilogue ----
#pragma unroll
    for (int mt = 0; mt < 2; mt++) {
        int row = m0 + wm * 32 + mt * 16 + (lane >> 2);
#pragma unroll
        for (int nt = 0; nt < 8; nt++) {
            int col = n0 + wn * 64 + nt * 8 + 2 * (lane & 3);
            float b0 = 0.f, b1 = 0.f;
            if (bias != nullptr) { b0 = bias[col]; b1 = bias[col + 1]; }
            float2 o0, o1;
            o0.x = acc[mt][nt][0] + b0; o0.y = acc[mt][nt][1] + b1;
            o1.x = acc[mt][nt][2] + b0; o1.y = acc[mt][nt][3] + b1;
            *(float2*)&C[(size_t)row * N + col] = o0;
            *(float2*)&C[(size_t)(row + 8) * N + col] = o1;
        }
    }
}

// ---------------------------------------------------------------------------
// RoPE (in place). x layout [S][stride], head h at col h*HD. cos/sin [S][HD].
// ---------------------------------------------------------------------------
__global__ void rope_kernel(float* __restrict__ x,
                            const float* __restrict__ cosp,
                            const float* __restrict__ sinp, int nh, int stride) {
    int idx = blockIdx.x * blockDim.x + threadIdx.x;
    int total = S_LEN * nh * 64;
    if (idx >= total) return;
    int d = idx & 63;
    int h = (idx >> 6) % nh;
    int s = idx / (nh * 64);
    float c1 = cosp[s * HD + d];
    float s1 = sinp[s * HD + d];
    float c2 = cosp[s * HD + d + 64];
    float s2 = sinp[s * HD + d + 64];
    float* row = x + (size_t)s * stride + h * HD;
    float x1 = row[d];
    float x2 = row[d + 64];
    row[d]      = x1 * c1 - x2 * s1;
    row[d + 64] = x2 * c2 + x1 * s2;
}

// ---------------------------------------------------------------------------
// Causal flash attention, fp32. BM=BN=64, D=128. 256 threads.
// KV comes from fused [S][512] buffer: K at col kvh*128, V at 256 + kvh*128.
// ---------------------------------------------------------------------------
#define QS_OFF   0
#define KS_OFF   (128 * 68)
#define VS_OFF   (KS_OFF + 128 * 68)
#define PS_OFF   (VS_OFF + 64 * 128)
#define RED_OFF  (PS_OFF + 64 * 68)
#define RM_OFF   (RED_OFF + 64 * 17)
#define RL_OFF   (RM_OFF + 64)
#define RS_OFF   (RL_OFF + 64)
#define FLASH_SMEM_FLOATS (RS_OFF + 64)
#define FLASH_SMEM_BYTES  (FLASH_SMEM_FLOATS * 4)

__global__ __launch_bounds__(256, 1)
void flash_kernel(const float* __restrict__ Q, const float* __restrict__ KV,
                  float* __restrict__ O) {
    extern __shared__ float sm[];
    float* Qs = sm + QS_OFF;
    float* Ks = sm + KS_OFF;
    float* Vs = sm + VS_OFF;
    float* Ps = sm + PS_OFF;
    float* red = sm + RED_OFF;
    float* row_m = sm + RM_OFF;
    float* row_l = sm + RL_OFF;
    float* row_scale = sm + RS_OFF;

    const int tid = threadIdx.x;
    const int tx = tid & 15;
    const int ty = tid >> 4;
    const int qt = (gridDim.x - 1) - blockIdx.x;
    const int h = blockIdx.y;
    const int kvh = h / NREP;
    const int s0 = qt * 64;
    const int koff = kvh * HD;
    const int voff = NKVH * HD + kvh * HD;

#pragma unroll
    for (int e = 0; e < 8; e++) {
        int lin = tid + e * 256;
        int row = lin >> 5;
        int dq = (lin & 31) * 4;
        float4 qv = *(const float4*)&Q[(size_t)(s0 + row) * (NH * HD) + h * HD + dq];
        Qs[(dq + 0) * 68 + row] = qv.x;
        Qs[(dq + 1) * 68 + row] = qv.y;
        Qs[(dq + 2) * 68 + row] = qv.z;
        Qs[(dq + 3) * 68 + row] = qv.w;
    }
    if (tid < 64) {
        row_m[tid] = -1e30f;
        row_l[tid] = 0.0f;
    }

    float acc[4][8];
#pragma unroll
    for (int i = 0; i < 4; i++)
#pragma unroll
        for (int c = 0; c < 8; c++) acc[i][c] = 0.0f;

    for (int jt = 0; jt <= qt; jt++) {
        const int j0 = jt * 64;
        __syncthreads();

#pragma unroll
        for (int e = 0; e < 8; e++) {
            int lin = tid + e * 256;
            int row = lin >> 5;
            int dq = (lin & 31) * 4;
            const float* kvrow = &KV[(size_t)(j0 + row) * KV_STRIDE];
            float4 kv4 = *(const float4*)&kvrow[koff + dq];
            Ks[(dq + 0) * 68 + row] = kv4.x;
            Ks[(dq + 1) * 68 + row] = kv4.y;
            Ks[(dq + 2) * 68 + row] = kv4.z;
            Ks[(dq + 3) * 68 + row] = kv4.w;
            *(float4*)&Vs[row * 128 + dq] = *(const float4*)&kvrow[voff + dq];
        }
        __syncthreads();

        float sc[4][4];
#pragma unroll
        for (int i = 0; i < 4; i++)
#pragma unroll
            for (int j = 0; j < 4; j++) sc[i][j] = 0.0f;

#pragma unroll 4
        for (int kk = 0; kk < 128; kk++) {
            float4 q4 = *(const float4*)&Qs[kk * 68 + ty * 4];
            float4 k4 = *(const float4*)&Ks[kk * 68 + tx * 4];
            float qa[4] = {q4.x, q4.y, q4.z, q4.w};
            float ka[4] = {k4.x, k4.y, k4.z, k4.w};
#pragma unroll
            for (int i = 0; i < 4; i++)
#pragma unroll
                for (int j = 0; j < 4; j++)
                    sc[i][j] += qa[i] * ka[j];
        }

#pragma unroll
        for (int i = 0; i < 4; i++) {
            int qrow = s0 + ty * 4 + i;
            float mx = -1e30f;
#pragma unroll
            for (int j = 0; j < 4; j++) {
                int kcol = j0 + tx * 4 + j;
                float v = sc[i][j] * SCALING;
                if (kcol > qrow) v = -1e9f;
                sc[i][j] = v;
                mx = fmaxf(mx, v);
            }
            red[(ty * 4 + i) * 17 + tx] = mx;
        }
        __syncthreads();

        if (tid < 64) {
            float mt = red[tid * 17];
#pragma unroll
            for (int t = 1; t < 16; t++) mt = fmaxf(mt, red[tid * 17 + t]);
            float m_old = row_m[tid];
            float m_new = fmaxf(m_old, mt);
            row_scale[tid] = __expf(m_old - m_new);
            row_m[tid] = m_new;
        }
        __syncthreads();

#pragma unroll
        for (int i = 0; i < 4; i++) {
            float m_r = row_m[ty * 4 + i];
            float s_part = 0.0f;
#pragma unroll
            for (int j = 0; j < 4; j++) {
                float p = __expf(sc[i][j] - m_r);
                Ps[(ty * 4 + i) * 68 + tx * 4 + j] = p;
                s_part += p;
            }
            red[(ty * 4 + i) * 17 + tx] = s_part;
        }
        __syncthreads();

        if (tid < 64) {
            float sum = 0.0f;
#pragma unroll
            for (int t = 0; t < 16; t++) sum += red[tid * 17 + t];
            row_l[tid] = row_l[tid] * row_scale[tid] + sum;
        }

        float rs[4];
#pragma unroll
        for (int i = 0; i < 4; i++) rs[i] = row_scale[ty * 4 + i];
#pragma unroll
        for (int i = 0; i < 4; i++)
#pragma unroll
            for (int c = 0; c < 8; c++) acc[i][c] *= rs[i];

#pragma unroll 2
        for (int j = 0; j < 64; j++) {
            float4 v0 = *(const float4*)&Vs[j * 128 + tx * 8];
            float4 v1 = *(const float4*)&Vs[j * 128 + tx * 8 + 4];
            float va[8] = {v0.x, v0.y, v0.z, v0.w, v1.x, v1.y, v1.z, v1.w};
            float p[4];
#pragma unroll
            for (int i = 0; i < 4; i++) p[i] = Ps[(ty * 4 + i) * 68 + j];
#pragma unroll
            for (int i = 0; i < 4; i++)
#pragma unroll
                for (int c = 0; c < 8; c++)
                    acc[i][c] += p[i] * va[c];
        }
    }

    __syncthreads();
#pragma unroll
    for (int i = 0; i < 4; i++) {
        int row = s0 + ty * 4 + i;
        float inv_l = 1.0f / row_l[ty * 4 + i];
        float4 o0, o1;
        o0.x = acc[i][0] * inv_l; o0.y = acc[i][1] * inv_l;
        o0.z = acc[i][2] * inv_l; o0.w = acc[i][3] * inv_l;
        o1.x = acc[i][4] * inv_l; o1.y = acc[i][5] * inv_l;
        o1.z = acc[i][6] * inv_l; o1.w = acc[i][7] * inv_l;
        float* dst = &O[(size_t)row * (NH * HD) + h * HD + tx * 8];
        *(float4*)&dst[0] = o0;
        *(float4*)&dst[4] = o1;
    }
}

// ---------------------------------------------------------------------------
// Launch
// ---------------------------------------------------------------------------
extern "C" void kernel_launch(void* const* d_in, const int* in_sizes, int n_in,
                              void* d_out, int out_size) {
    const float* hs   = (const float*)d_in[0];
    const float* cosp = (const float*)d_in[1];
    const float* sinp = (const float*)d_in[2];
    // d_in[3] = attention_mask (pure causal; applied analytically)
    const float* Wq = (const float*)d_in[4];
    const float* bq = (const float*)d_in[5];
    const float* Wk = (const float*)d_in[6];
    const float* bk = (const float*)d_in[7];
    const float* Wv = (const float*)d_in[8];
    const float* bv = (const float*)d_in[9];
    const float* Wo = (const float*)d_in[10];
    float* out = (float*)d_out;

    float *q, *kv, *attn, *wqt, *wkvt, *wot, *bkv;
    cudaGetSymbolAddress((void**)&q, g_q);
    cudaGetSymbolAddress((void**)&kv, g_kv);
    cudaGetSymbolAddress((void**)&attn, g_attn);
    cudaGetSymbolAddress((void**)&wqt, g_wqt);
    cudaGetSymbolAddress((void**)&wkvt, g_wkvt);
    cudaGetSymbolAddress((void**)&wot, g_wot);
    cudaGetSymbolAddress((void**)&bkv, g_bkv);

    // Concat biases [bk ; bv]
    cudaMemcpyAsync(bkv, bk, NKVH * HD * sizeof(float), cudaMemcpyDeviceToDevice);
    cudaMemcpyAsync(bkv + NKVH * HD, bv, NKVH * HD * sizeof(float),
                    cudaMemcpyDeviceToDevice);

    // Transpose + tf32-round weights
    dim3 tb(32, 8);
    transpose_round_kernel<<<dim3((NH * HD) / 32, HID / 32), tb>>>(Wq, wqt, HID, NH * HD);
    transpose_round_kernel<<<dim3((NKVH * HD) / 32, HID / 32), tb>>>(Wk, wkvt, HID, NKVH * HD);
    transpose_round_kernel<<<dim3((NKVH * HD) / 32, HID / 32), tb>>>(
        Wv, wkvt + (size_t)(NKVH * HD) * HID, HID, NKVH * HD);
    transpose_round_kernel<<<dim3(HID / 32, (NH * HD) / 32), tb>>>(Wo, wot, NH * HD, HID);

    cudaFuncSetAttribute(gemm_mma_kernel, cudaFuncAttributeMaxDynamicSharedMemorySize,
                         GEMM_SMEM_BYTES);

    // Projections (tf32 mma.sync)
    gemm_mma_kernel<<<dim3((NH * HD) / 128, S_LEN / 128), 256, GEMM_SMEM_BYTES>>>(
        hs, wqt, bq, q, S_LEN, NH * HD, HID);
    gemm_mma_kernel<<<dim3(KV_STRIDE / 128, S_LEN / 128), 256, GEMM_SMEM_BYTES>>>(
        hs, wkvt, bkv, kv, S_LEN, KV_STRIDE, HID);

    // RoPE (q stride 2048; k part of kv stride 512)
    rope_kernel<<<(S_LEN * NH * 64) / 256, 256>>>(q, cosp, sinp, NH, NH * HD);
    rope_kernel<<<(S_LEN * NKVH * 64) / 256, 256>>>(kv, cosp, sinp, NKVH, KV_STRIDE);

    // Attention (fp32 flash)
    cudaFuncSetAttribute(flash_kernel, cudaFuncAttributeMaxDynamicSharedMemorySize,
                         FLASH_SMEM_BYTES);
    flash_kernel<<<dim3(S_LEN / 64, NH), 256, FLASH_SMEM_BYTES>>>(q, kv, attn);

    // Output projection (tf32 mma.sync)
    gemm_mma_kernel<<<dim3(HID / 128, S_LEN / 128), 256, GEMM_SMEM_BYTES>>>(
        attn, wot, nullptr, out, S_LEN, HID, NH * HD);
}